// round 2
// baseline (speedup 1.0000x reference)
#include <cuda_runtime.h>

#define B_ 128
#define N_ 4096
#define K_ 100
#define P_ 4096

// Scratch (device global — no allocation in kernel_launch, per harness rules)
__device__ double g_loss[B_];

// ---------------------------------------------------------------------------
// Fused per-row kernel: shift detection + K=100 circular gather + nearest
// neighbor + variance. One block per row b, 512 threads.
//
// Semantics (exactly matching the JAX reference):
//   u = target / amp
//   j_left  = first i with u[i] >= 0        (0 if none: jnp.argmax on all-False)
//   m_right = first r with u[N-1-r] <= 0    (0 if none)
//   left_case = (u[N-1] < 0) && (u[0] < 0)
//   shift = left_case ? -(j_left+1) : m_right
//   src(k) = (k - shift) mod N  (non-negative Python mod)
//   X100[k]  = Xffp[b][src];  dvals[k] = t[src]/a[src] - p[src]/a[src]
//   nn[p] = argmin_k |pointx[p] - X100[k]|  (first-index tie-break: strict <,
//           ascending k)
//   loss[b] = var(dvals[nn[p]] for p in 1..P-1), ddof=0
// ---------------------------------------------------------------------------
__global__ void __launch_bounds__(512, 2)
k_fused(const float* __restrict__ preds,
        const float* __restrict__ target,
        const float* __restrict__ Xffp,
        const float* __restrict__ amp,
        const float* __restrict__ pointx)
{
    const int b   = blockIdx.x;
    const int tid = threadIdx.x;          // blockDim.x == 512
    const int w   = tid >> 5, l = tid & 31;

    const float* t = target + (size_t)b * N_;
    const float* a = amp    + (size_t)b * N_;
    const float* p = preds  + (size_t)b * N_;
    const float* x = Xffp   + (size_t)b * N_;

    // ---- Phase 1: scan for min index with u>=0 and max index with u<=0 ----
    int minGe = N_;
    int maxLe = -1;
    #pragma unroll
    for (int j = 0; j < N_ / 512; j++) {
        int i = tid + j * 512;
        float u = t[i] / a[i];
        if (u >= 0.0f && i < minGe) minGe = i;
        if (u <= 0.0f && i > maxLe) maxLe = i;
    }
    #pragma unroll
    for (int o = 16; o > 0; o >>= 1) {
        minGe = min(minGe, __shfl_down_sync(0xffffffffu, minGe, o));
        maxLe = max(maxLe, __shfl_down_sync(0xffffffffu, maxLe, o));
    }
    __shared__ int sMin[16], sMax[16];
    __shared__ int sShift;
    if (l == 0) { sMin[w] = minGe; sMax[w] = maxLe; }
    __syncthreads();
    if (tid == 0) {
        int mg = N_, ml = -1;
        #pragma unroll
        for (int i = 0; i < 16; i++) { mg = min(mg, sMin[i]); ml = max(ml, sMax[i]); }
        int j_left  = (mg == N_) ? 0 : mg;
        int m_right = (ml < 0)   ? 0 : (N_ - 1 - ml);
        float first = t[0]      / a[0];
        float last  = t[N_ - 1] / a[N_ - 1];
        bool left_case = (last < 0.0f) && (first < 0.0f);
        sShift = left_case ? -(j_left + 1) : m_right;
    }
    __syncthreads();

    // ---- Phase 2: gather the K=100 shifted values into shared ----
    __shared__ float sX[K_];
    __shared__ float sD[K_];
    if (tid < K_) {
        int src = (tid - sShift) % N_;
        if (src < 0) src += N_;
        float av = a[src];
        sX[tid] = x[src];
        sD[tid] = t[src] / av - p[src] / av;   // u - u_uifft, two divisions as in ref
    }
    __syncthreads();

    // ---- Phase 3: NN scan, 8 points per thread in registers ----
    float px[8], best[8];
    int   bi[8];
    #pragma unroll
    for (int j = 0; j < 8; j++) {
        px[j]   = pointx[tid + j * 512];
        best[j] = __int_as_float(0x7f7fffff);   // FLT_MAX
        bi[j]   = 0;
    }
    #pragma unroll 4
    for (int k = 0; k < K_; k++) {
        float xk = sX[k];
        #pragma unroll
        for (int j = 0; j < 8; j++) {
            float d = fabsf(px[j] - xk);
            if (d < best[j]) { best[j] = d; bi[j] = k; }
        }
    }

    // ---- Phase 4: variance over p = 1 .. P-1 (double accumulation) ----
    double s = 0.0, s2 = 0.0;
    #pragma unroll
    for (int j = 0; j < 8; j++) {
        int pi = tid + j * 512;
        if (pi >= 1) {                       // diff[:, 1:] excludes point 0
            float dv = sD[bi[j]];
            s  += (double)dv;
            s2 += (double)dv * (double)dv;
        }
    }
    #pragma unroll
    for (int o = 16; o > 0; o >>= 1) {
        s  += __shfl_down_sync(0xffffffffu, s,  o);
        s2 += __shfl_down_sync(0xffffffffu, s2, o);
    }
    __shared__ double rs[16], rs2[16];
    if (l == 0) { rs[w] = s; rs2[w] = s2; }
    __syncthreads();
    if (w == 0) {
        s  = (l < 16) ? rs [l] : 0.0;
        s2 = (l < 16) ? rs2[l] : 0.0;
        #pragma unroll
        for (int o = 8; o > 0; o >>= 1) {
            s  += __shfl_down_sync(0xffffffffu, s,  o);
            s2 += __shfl_down_sync(0xffffffffu, s2, o);
        }
        if (l == 0) {
            const double M = (double)(P_ - 1);   // 4095, ddof=0
            double mean = s / M;
            g_loss[b] = s2 / M - mean * mean;
        }
    }
}

// ---------------------------------------------------------------------------
// Final: mean over the 128 per-row losses -> scalar f32 output.
// ---------------------------------------------------------------------------
__global__ void k_final(float* __restrict__ out)
{
    const int tid = threadIdx.x;          // blockDim.x == 128
    double v = g_loss[tid];
    #pragma unroll
    for (int o = 16; o > 0; o >>= 1) v += __shfl_down_sync(0xffffffffu, v, o);
    __shared__ double r[4];
    const int w = tid >> 5, l = tid & 31;
    if (l == 0) r[w] = v;
    __syncthreads();
    if (tid == 0) out[0] = (float)((r[0] + r[1] + r[2] + r[3]) / (double)B_);
}

// ---------------------------------------------------------------------------
// Inputs (metadata order): preds, target, Xffp, dXffp_Amp, pointx
// Output: scalar float32
// ---------------------------------------------------------------------------
extern "C" void kernel_launch(void* const* d_in, const int* in_sizes, int n_in,
                              void* d_out, int out_size)
{
    const float* preds  = (const float*)d_in[0];
    const float* target = (const float*)d_in[1];
    const float* Xffp   = (const float*)d_in[2];
    const float* amp    = (const float*)d_in[3];
    const float* pointx = (const float*)d_in[4];

    k_fused<<<B_, 512>>>(preds, target, Xffp, amp, pointx);
    k_final<<<1, 128>>>((float*)d_out);
}

// round 3
// speedup vs baseline: 1.3622x; 1.3622x over previous
#include <cuda_runtime.h>

#define B_ 128
#define N_ 4096
#define K_ 100
#define P_ 4096

// Device globals (no allocation in kernel_launch, per harness rules)
__device__ double g_loss[B_];
__device__ int    g_count = 0;   // reset to 0 by the last block every launch

#define F_INF __int_as_float(0x7f800000)

// ---------------------------------------------------------------------------
// Single fused kernel. One block per row b, 512 threads.
//   Phase 1: scan u = target/amp for first u>=0 and last u<=0  -> shift
//   Phase 2: gather the K=100 circularly shifted X / dvals into shared
//   Phase 3: stable rank-sort of the K values (keep orig index for tie-break)
//   Phase 4: per point, branchless binary search (lower_bound) + 2-candidate
//            nearest-neighbor fixup, exact jnp.argmin first-index tie-break
//   Phase 5: per-row variance (ddof=0, points 1..P-1), double accumulation
//   Phase 6: last finished block reduces the 128 row losses -> mean -> d_out
// ---------------------------------------------------------------------------
__global__ void __launch_bounds__(512, 2)
k_fused(const float* __restrict__ preds,
        const float* __restrict__ target,
        const float* __restrict__ Xffp,
        const float* __restrict__ amp,
        const float* __restrict__ pointx,
        float* __restrict__ out)
{
    const int b   = blockIdx.x;
    const int tid = threadIdx.x;          // 512
    const int w   = tid >> 5, l = tid & 31;

    const float* t = target + (size_t)b * N_;
    const float* a = amp    + (size_t)b * N_;
    const float* p = preds  + (size_t)b * N_;
    const float* x = Xffp   + (size_t)b * N_;

    // ---- Phase 1: min index with u>=0, max index with u<=0 ----
    int minGe = N_;
    int maxLe = -1;
    #pragma unroll
    for (int j = 0; j < N_ / 512; j++) {
        int i = tid + j * 512;
        float u = t[i] / a[i];
        if (u >= 0.0f && i < minGe) minGe = i;
        if (u <= 0.0f && i > maxLe) maxLe = i;
    }
    #pragma unroll
    for (int o = 16; o > 0; o >>= 1) {
        minGe = min(minGe, __shfl_down_sync(0xffffffffu, minGe, o));
        maxLe = max(maxLe, __shfl_down_sync(0xffffffffu, maxLe, o));
    }
    __shared__ int sMin[16], sMax[16];
    __shared__ int sShift;
    if (l == 0) { sMin[w] = minGe; sMax[w] = maxLe; }
    __syncthreads();
    if (tid == 0) {
        int mg = N_, ml = -1;
        #pragma unroll
        for (int i = 0; i < 16; i++) { mg = min(mg, sMin[i]); ml = max(ml, sMax[i]); }
        int j_left  = (mg == N_) ? 0 : mg;                 // jnp.argmax all-False -> 0
        int m_right = (ml < 0)   ? 0 : (N_ - 1 - ml);
        float first = t[0]      / a[0];
        float last  = t[N_ - 1] / a[N_ - 1];
        bool left_case = (last < 0.0f) && (first < 0.0f);
        sShift = left_case ? -(j_left + 1) : m_right;
    }
    __syncthreads();

    // ---- Phase 2: gather K=100 shifted values ----
    __shared__ float sX[K_], sD[K_];
    if (tid < K_) {
        int src = (tid - sShift) % N_;
        if (src < 0) src += N_;
        float av = a[src];
        sX[tid] = x[src];
        sD[tid] = t[src] / av - p[src] / av;   // u - u_uifft (two divisions, as in ref)
    }
    __syncthreads();

    // ---- Phase 3: stable rank-sort (value asc, orig index asc on ties) ----
    __shared__ float sXs[K_], sDs[K_];
    __shared__ int   sIs[K_];
    if (tid < K_) {
        float v = sX[tid];
        int rank = 0;
        #pragma unroll 4
        for (int j = 0; j < K_; j++) {
            float u = sX[j];                    // broadcast LDS, conflict-free
            rank += (u < v) || (u == v && j < tid);
        }
        sXs[rank] = v;
        sDs[rank] = sD[tid];
        sIs[rank] = tid;
    }
    __syncthreads();

    // ---- Phase 4+5: binary-search NN + variance, 8 points/thread ----
    double s = 0.0, s2 = 0.0;
    #pragma unroll
    for (int j = 0; j < 8; j++) {
        const int pi = tid + j * 512;
        const float px = pointx[pi];
        // branchless lower_bound: pos = #elements < px
        int pos = 0;
        #pragma unroll
        for (int step = 64; step >= 1; step >>= 1)
            if (pos + step <= K_ && sXs[pos + step - 1] < px) pos += step;
        // two candidates: pos-1 (strictly < px) and pos (>= px)
        float dL = (pos > 0)  ? fabsf(px - sXs[pos - 1]) : F_INF;
        float dR = (pos < K_) ? fabsf(px - sXs[pos])     : F_INF;
        int   iL = (pos > 0)  ? sIs[pos - 1] : 0x7fffffff;
        int   iR = (pos < K_) ? sIs[pos]     : 0x7fffffff;
        bool takeL = (dL < dR) || (dL == dR && iL < iR);   // first-index tie-break
        float dv = takeL ? sDs[pos - 1] : sDs[pos];
        if (pi >= 1) {                         // diff[:, 1:] excludes point 0
            s  += (double)dv;
            s2 += (double)dv * (double)dv;
        }
    }
    #pragma unroll
    for (int o = 16; o > 0; o >>= 1) {
        s  += __shfl_down_sync(0xffffffffu, s,  o);
        s2 += __shfl_down_sync(0xffffffffu, s2, o);
    }
    __shared__ double rs[16], rs2[16];
    if (l == 0) { rs[w] = s; rs2[w] = s2; }
    __syncthreads();
    if (tid == 0) {
        double ts1 = 0.0, ts2 = 0.0;
        #pragma unroll
        for (int i = 0; i < 16; i++) { ts1 += rs[i]; ts2 += rs2[i]; }
        const double M = (double)(P_ - 1);     // 4095, ddof=0
        double mean = ts1 / M;
        g_loss[b] = ts2 / M - mean * mean;
    }

    // ---- Phase 6: last block computes the mean over all rows ----
    __shared__ int sLast;
    if (tid == 0) {
        __threadfence();                        // make g_loss[b] visible
        sLast = (atomicAdd(&g_count, 1) == B_ - 1);
    }
    __syncthreads();
    if (sLast) {
        double v = (tid < B_) ? g_loss[tid] : 0.0;
        #pragma unroll
        for (int o = 16; o > 0; o >>= 1) v += __shfl_down_sync(0xffffffffu, v, o);
        __shared__ double r[16];
        if (l == 0) r[w] = v;
        __syncthreads();
        if (tid == 0) {
            double acc = 0.0;
            #pragma unroll
            for (int i = 0; i < 16; i++) acc += r[i];
            out[0] = (float)(acc / (double)B_);
            g_count = 0;                        // reset for next graph replay
        }
    }
}

// ---------------------------------------------------------------------------
// Inputs (metadata order): preds, target, Xffp, dXffp_Amp, pointx
// Output: scalar float32
// ---------------------------------------------------------------------------
extern "C" void kernel_launch(void* const* d_in, const int* in_sizes, int n_in,
                              void* d_out, int out_size)
{
    const float* preds  = (const float*)d_in[0];
    const float* target = (const float*)d_in[1];
    const float* Xffp   = (const float*)d_in[2];
    const float* amp    = (const float*)d_in[3];
    const float* pointx = (const float*)d_in[4];

    k_fused<<<B_, 512>>>(preds, target, Xffp, amp, pointx, (float*)d_out);
}

// round 4
// speedup vs baseline: 1.5922x; 1.1688x over previous
#include <cuda_runtime.h>

#define B_ 128
#define N_ 4096
#define K_ 100
#define P_ 4096
#define T_ 1024           // threads per block

// Device globals (no allocation in kernel_launch, per harness rules)
__device__ double g_loss[B_];
__device__ int    g_count = 0;   // reset to 0 by the last block every launch

#define F_INF __int_as_float(0x7f800000)

// ---------------------------------------------------------------------------
// Single fused kernel. One block per row b, 1024 threads.
//   Phase 1: sign-only scan of u = target/amp (no division: sign(u) =
//            signbit(t) XOR signbit(a), with t==0 => u==0) -> shift
//   Phase 2: gather the K=100 circularly shifted X / dvals into shared
//   Phase 3: stable rank-sort of the K values (orig index kept for tie-break)
//   Phase 4: per point, branchless binary search (lower_bound) + 2-candidate
//            NN fixup, exact jnp.argmin first-index tie-break
//   Phase 5: per-row variance (ddof=0, points 1..P-1), double accumulation
//   Phase 6: last finished block reduces the 128 row losses -> mean -> d_out
// ---------------------------------------------------------------------------
__global__ void __launch_bounds__(T_, 1)
k_fused(const float* __restrict__ preds,
        const float* __restrict__ target,
        const float* __restrict__ Xffp,
        const float* __restrict__ amp,
        const float* __restrict__ pointx,
        float* __restrict__ out)
{
    const int b   = blockIdx.x;
    const int tid = threadIdx.x;          // 1024
    const int w   = tid >> 5, l = tid & 31;

    const float* t = target + (size_t)b * N_;
    const float* a = amp    + (size_t)b * N_;
    const float* p = preds  + (size_t)b * N_;
    const float* x = Xffp   + (size_t)b * N_;

    // Prefetch pointx early: independent of phases 1-3, overlaps their latency.
    float px[4];
    #pragma unroll
    for (int j = 0; j < 4; j++) px[j] = pointx[tid + j * T_];

    // ---- Phase 1: min index with u>=0, max index with u<=0 (sign-only) ----
    int minGe = N_;
    int maxLe = -1;
    #pragma unroll
    for (int j = 0; j < N_ / T_; j++) {
        int i = tid + j * T_;
        float tv = t[i], av = a[i];
        int  sgn  = __float_as_int(tv) ^ __float_as_int(av); // sign of t/a
        bool zer  = (tv == 0.0f);                            // u == 0 (also -0)
        bool ge   = zer || (sgn >= 0);                       // u >= 0
        bool le   = zer || (sgn <  0);                       // u <= 0
        if (ge && i < minGe) minGe = i;
        if (le && i > maxLe) maxLe = i;
    }
    #pragma unroll
    for (int o = 16; o > 0; o >>= 1) {
        minGe = min(minGe, __shfl_down_sync(0xffffffffu, minGe, o));
        maxLe = max(maxLe, __shfl_down_sync(0xffffffffu, maxLe, o));
    }
    __shared__ int sMin[32], sMax[32];
    __shared__ int sShift;
    if (l == 0) { sMin[w] = minGe; sMax[w] = maxLe; }
    __syncthreads();
    if (tid == 0) {
        int mg = N_, ml = -1;
        #pragma unroll
        for (int i = 0; i < 32; i++) { mg = min(mg, sMin[i]); ml = max(ml, sMax[i]); }
        int j_left  = (mg == N_) ? 0 : mg;                 // jnp.argmax all-False -> 0
        int m_right = (ml < 0)   ? 0 : (N_ - 1 - ml);
        float first = t[0]      / a[0];
        float last  = t[N_ - 1] / a[N_ - 1];
        bool left_case = (last < 0.0f) && (first < 0.0f);
        sShift = left_case ? -(j_left + 1) : m_right;
    }
    __syncthreads();

    // ---- Phase 2: gather K=100 shifted values ----
    __shared__ float sX[K_], sD[K_];
    if (tid < K_) {
        int src = (tid - sShift) % N_;
        if (src < 0) src += N_;
        float av = a[src];
        sX[tid] = x[src];
        sD[tid] = t[src] / av - p[src] / av;   // u - u_uifft (two divisions, as in ref)
    }
    __syncthreads();

    // ---- Phase 3: stable rank-sort (value asc, orig index asc on ties) ----
    __shared__ float sXs[K_], sDs[K_];
    __shared__ int   sIs[K_];
    if (tid < K_) {
        float v = sX[tid];
        int rank = 0;
        #pragma unroll 5
        for (int j = 0; j < K_; j++) {
            float u = sX[j];                    // broadcast LDS, conflict-free
            rank += (u < v) || (u == v && j < tid);
        }
        sXs[rank] = v;
        sDs[rank] = sD[tid];
        sIs[rank] = tid;
    }
    __syncthreads();

    // ---- Phase 4+5: binary-search NN + variance, 4 points/thread ----
    double s = 0.0, s2 = 0.0;
    #pragma unroll
    for (int j = 0; j < 4; j++) {
        const int pi = tid + j * T_;
        const float pv = px[j];
        // branchless lower_bound: pos = #elements < pv
        int pos = 0;
        #pragma unroll
        for (int step = 64; step >= 1; step >>= 1)
            if (pos + step <= K_ && sXs[pos + step - 1] < pv) pos += step;
        // two candidates: pos-1 (strictly < pv) and pos (>= pv)
        float dL = (pos > 0)  ? fabsf(pv - sXs[pos - 1]) : F_INF;
        float dR = (pos < K_) ? fabsf(pv - sXs[pos])     : F_INF;
        int   iL = (pos > 0)  ? sIs[pos - 1] : 0x7fffffff;
        int   iR = (pos < K_) ? sIs[pos]     : 0x7fffffff;
        bool takeL = (dL < dR) || (dL == dR && iL < iR);   // first-index tie-break
        float dv = takeL ? sDs[pos - 1] : sDs[pos];
        if (pi >= 1) {                         // diff[:, 1:] excludes point 0
            s  += (double)dv;
            s2 += (double)dv * (double)dv;
        }
    }
    #pragma unroll
    for (int o = 16; o > 0; o >>= 1) {
        s  += __shfl_down_sync(0xffffffffu, s,  o);
        s2 += __shfl_down_sync(0xffffffffu, s2, o);
    }
    __shared__ double rs[32], rs2[32];
    if (l == 0) { rs[w] = s; rs2[w] = s2; }
    __syncthreads();
    if (tid == 0) {
        double ts1 = 0.0, ts2 = 0.0;
        #pragma unroll
        for (int i = 0; i < 32; i++) { ts1 += rs[i]; ts2 += rs2[i]; }
        const double M = (double)(P_ - 1);     // 4095, ddof=0
        double mean = ts1 / M;
        g_loss[b] = ts2 / M - mean * mean;
    }

    // ---- Phase 6: last block computes the mean over all rows ----
    __shared__ int sLast;
    if (tid == 0) {
        __threadfence();                        // make g_loss[b] visible
        sLast = (atomicAdd(&g_count, 1) == B_ - 1);
    }
    __syncthreads();
    if (sLast) {
        double v = (tid < B_) ? g_loss[tid] : 0.0;
        #pragma unroll
        for (int o = 16; o > 0; o >>= 1) v += __shfl_down_sync(0xffffffffu, v, o);
        __shared__ double r[32];
        if (l == 0) r[w] = v;
        __syncthreads();
        if (tid == 0) {
            double acc = 0.0;
            #pragma unroll
            for (int i = 0; i < 4; i++) acc += r[i];   // only warps 0-3 hold rows
            out[0] = (float)(acc / (double)B_);
            g_count = 0;                        // reset for next graph replay
        }
    }
}

// ---------------------------------------------------------------------------
// Inputs (metadata order): preds, target, Xffp, dXffp_Amp, pointx
// Output: scalar float32
// ---------------------------------------------------------------------------
extern "C" void kernel_launch(void* const* d_in, const int* in_sizes, int n_in,
                              void* d_out, int out_size)
{
    const float* preds  = (const float*)d_in[0];
    const float* target = (const float*)d_in[1];
    const float* Xffp   = (const float*)d_in[2];
    const float* amp    = (const float*)d_in[3];
    const float* pointx = (const float*)d_in[4];

    k_fused<<<B_, T_>>>(preds, target, Xffp, amp, pointx, (float*)d_out);
}